// round 1
// baseline (speedup 1.0000x reference)
#include <cuda_runtime.h>
#include <math.h>

// TriangularSylvesterNeRF: Z=32, K=4, H=128, B=32768
// Fused single kernel: per CTA of 32 samples,
//   1) load h tile (transposed+padded) to smem
//   2) small GEMMs -> diag1(tanh), diag2(tanh), b  (kept in smem)
//   3) for k in 0..3:  D_k = h @ Wd_k.T + bd_k  (32 x 1024, in smem),
//      then the flow step (two triangular matvecs via warp shuffles),
//      z and partial log|det| live in registers (1 warp owns 4 samples).
// Never materializes full_d to global memory.

#define ZZ 32
#define KK 4
#define HH 128
#define TM 32           // samples per CTA
#define NTHREADS 256
#define NWARPS 8
#define DP 33           // padded row pitch for Ds (Z+1)

#define SMEM_FLOATS (HH*33 + TM*ZZ*DP + 3*TM*HH)
#define SMEM_BYTES  (SMEM_FLOATS * 4)

__global__ __launch_bounds__(NTHREADS, 1)
void sylv_kernel(const float* __restrict__ z0, const float* __restrict__ h,
                 const float* __restrict__ Wd, const float* __restrict__ bd,
                 const float* __restrict__ Wd1, const float* __restrict__ bd1,
                 const float* __restrict__ Wd2, const float* __restrict__ bd2,
                 const float* __restrict__ Wb, const float* __restrict__ bb,
                 float* __restrict__ out_z, float* __restrict__ out_ld)
{
    extern __shared__ float sm[];
    float* HsT = sm;                     // [HH][33]  h tile transposed, padded
    float* Ds  = HsT + HH*33;            // [TM][ZZ*DP]  D_k slab
    float* d1s = Ds + TM*ZZ*DP;          // [TM][128]  tanh(h@Wd1.T+bd1), idx = j*4+k
    float* d2s = d1s + TM*HH;            // [TM][128]
    float* bs  = d2s + TM*HH;            // [TM][128]

    const int tid  = threadIdx.x;
    const int warp = tid >> 5;
    const int lane = tid & 31;
    const int m0   = blockIdx.x * TM;

    // ---- load h tile: global coalesced read, padded-transpose store ----
    for (int idx = tid; idx < TM * HH; idx += NTHREADS) {
        int m = idx >> 7, hh = idx & 127;
        HsT[hh * 33 + m] = h[(size_t)(m0 + m) * HH + hh];
    }
    __syncthreads();

    // ---- small GEMMs: diag1, diag2, b  (lane = sample m, warp strides cols) ----
    for (int col = warp; col < 3 * HH; col += NWARPS) {
        int matid = col >> 7;       // 0:Wd1(tanh) 1:Wd2(tanh) 2:Wb
        int c = col & 127;
        const float* Wrow; float bias;
        if (matid == 0)      { Wrow = Wd1; bias = bd1[c]; }
        else if (matid == 1) { Wrow = Wd2; bias = bd2[c]; }
        else                 { Wrow = Wb;  bias = bb[c];  }
        const float4* w4 = (const float4*)(Wrow + (size_t)c * HH);
        float acc = bias;
        #pragma unroll 8
        for (int q = 0; q < 32; q++) {
            float4 w = w4[q];
            acc += HsT[(4*q+0)*33 + lane] * w.x
                 + HsT[(4*q+1)*33 + lane] * w.y
                 + HsT[(4*q+2)*33 + lane] * w.z
                 + HsT[(4*q+3)*33 + lane] * w.w;
        }
        if (matid < 2) acc = tanhf(acc);
        float* dst = (matid == 0) ? d1s : (matid == 1 ? d2s : bs);
        dst[lane * HH + c] = acc;
    }

    // ---- per-sample flow state in registers: warp owns samples warp*4+s ----
    float zreg[4], ldp[4];
    #pragma unroll
    for (int s = 0; s < 4; s++) {
        int m = warp * 4 + s;
        zreg[s] = z0[(size_t)(m0 + m) * ZZ + lane];
        ldp[s]  = 0.0f;
    }

    for (int k = 0; k < KK; k++) {
        __syncthreads();  // Ds free to overwrite; (k==0) small GEMMs done

        // ---- main GEMM: Ds[m][i*33+j] = h_m . Wd[(i*32+j)*4+k] + bd ----
        // each warp computes 8 consecutive columns for all 32 samples (lane = m)
        #pragma unroll 1
        for (int pass = 0; pass < 1024 / (NWARPS * 8); pass++) {
            int nbase = (pass * NWARPS + warp) * 8;
            float acc[8];
            const float4* w4[8];
            #pragma unroll
            for (int c = 0; c < 8; c++) {
                int row = (nbase + c) * KK + k;          // flat = i*128 + j*4 + k
                acc[c] = bd[row];
                w4[c]  = (const float4*)(Wd + (size_t)row * HH);
            }
            #pragma unroll 4
            for (int q = 0; q < 32; q++) {
                float h0 = HsT[(4*q+0)*33 + lane];
                float h1 = HsT[(4*q+1)*33 + lane];
                float h2 = HsT[(4*q+2)*33 + lane];
                float h3 = HsT[(4*q+3)*33 + lane];
                #pragma unroll
                for (int c = 0; c < 8; c++) {
                    float4 w = w4[c][q];                  // uniform across warp
                    acc[c] += h0*w.x + h1*w.y + h2*w.z + h3*w.w;
                }
            }
            int i = nbase >> 5, j0 = nbase & 31;          // 8 cols stay in one i row
            #pragma unroll
            for (int c = 0; c < 8; c++)
                Ds[lane * (ZZ*DP) + i * DP + j0 + c] = acc[c];
        }
        __syncthreads();

        // ---- flow step k ----
        const bool flip = (k & 1);
        #pragma unroll
        for (int s = 0; s < 4; s++) {
            int m = warp * 4 + s;
            const float* Dm = Ds + m * (ZZ*DP);
            // z_per[lane]
            float zp = flip ? __shfl_sync(0xffffffffu, zreg[s], 31 - lane) : zreg[s];
            // pre[j=lane] = b + z_per[j]*diag2[j] + sum_{i>j} z_per[i]*D[i][j]
            float pre = bs[m*HH + lane*KK + k] + zp * d2s[m*HH + lane*KK + k];
            #pragma unroll
            for (int i = 1; i < ZZ; i++) {
                float zpi = __shfl_sync(0xffffffffu, zp, i);
                if (i > lane) pre += zpi * Dm[i * DP + lane];
            }
            float t = tanhf(pre);
            // dz[i=lane] = t[i]*diag1[i] + sum_{j>i} t[j]*D[i][j]
            float d1  = d1s[m*HH + lane*KK + k];
            float d2v = d2s[m*HH + lane*KK + k];
            float dacc = t * d1;
            #pragma unroll
            for (int j = 1; j < ZZ; j++) {
                float tj = __shfl_sync(0xffffffffu, t, j);
                if (j > lane) dacc += tj * Dm[lane * DP + j];
            }
            float dz = flip ? __shfl_sync(0xffffffffu, dacc, 31 - lane) : dacc;
            zreg[s] += dz;
            // log-det contribution (index j = lane)
            float dj = fmaf(1.0f - t * t, d1 * d2v, 1.0f);
            ldp[s] += logf(fabsf(dj));
        }
    }

    // ---- outputs: z (B,32) then log_det (B,) ----
    #pragma unroll
    for (int s = 0; s < 4; s++) {
        int m = warp * 4 + s;
        out_z[(size_t)(m0 + m) * ZZ + lane] = zreg[s];
        float v = ldp[s];
        #pragma unroll
        for (int off = 16; off; off >>= 1)
            v += __shfl_down_sync(0xffffffffu, v, off);
        if (lane == 0) out_ld[m0 + m] = v;
    }
}

extern "C" void kernel_launch(void* const* d_in, const int* in_sizes, int n_in,
                              void* d_out, int out_size)
{
    const float* z0  = (const float*)d_in[0];
    const float* h   = (const float*)d_in[1];
    const float* Wd  = (const float*)d_in[2];
    const float* bd  = (const float*)d_in[3];
    const float* Wd1 = (const float*)d_in[4];
    const float* bd1 = (const float*)d_in[5];
    const float* Wd2 = (const float*)d_in[6];
    const float* bd2 = (const float*)d_in[7];
    const float* Wb  = (const float*)d_in[8];
    const float* bb  = (const float*)d_in[9];
    // d_in[10] = is_test (ignored; reference path with is_test=0)

    const int B = in_sizes[0] / ZZ;   // 32768
    float* out   = (float*)d_out;
    float* out_z = out;               // B*Z floats
    float* out_ld = out + (size_t)B * ZZ;

    cudaFuncSetAttribute(sylv_kernel,
                         cudaFuncAttributeMaxDynamicSharedMemorySize, SMEM_BYTES);

    sylv_kernel<<<B / TM, NTHREADS, SMEM_BYTES>>>(
        z0, h, Wd, bd, Wd1, bd1, Wd2, bd2, Wb, bb, out_z, out_ld);
}

// round 3
// speedup vs baseline: 1.0001x; 1.0001x over previous
#include <cuda_runtime.h>
#include <math.h>

// TriangularSylvesterNeRF: Z=32, K=4, H=128, B=32768
// Fused single kernel: per CTA of 32 samples,
//   1) load h tile (transposed+padded) to smem
//   2) small GEMMs -> diag1(tanh), diag2(tanh), b  (kept in smem)
//   3) for k in 0..3:  D_k = h @ Wd_k.T + bd_k  (32 x 1024, in smem),
//      then the flow step (two triangular matvecs via warp shuffles),
//      z and partial log|det| live in registers (1 warp owns 4 samples).
// Never materializes full_d to global memory.

#define ZZ 32
#define KK 4
#define HH 128
#define TM 32           // samples per CTA
#define NTHREADS 256
#define NWARPS 8
#define DP 33           // padded row pitch for Ds (Z+1)

#define SMEM_FLOATS (HH*33 + TM*ZZ*DP + 3*TM*HH)
#define SMEM_BYTES  (SMEM_FLOATS * 4)

__global__ __launch_bounds__(NTHREADS, 1)
void sylv_kernel(const float* __restrict__ z0, const float* __restrict__ h,
                 const float* __restrict__ Wd, const float* __restrict__ bd,
                 const float* __restrict__ Wd1, const float* __restrict__ bd1,
                 const float* __restrict__ Wd2, const float* __restrict__ bd2,
                 const float* __restrict__ Wb, const float* __restrict__ bb,
                 float* __restrict__ out_z, float* __restrict__ out_ld)
{
    extern __shared__ float sm[];
    float* HsT = sm;                     // [HH][33]  h tile transposed, padded
    float* Ds  = HsT + HH*33;            // [TM][ZZ*DP]  D_k slab
    float* d1s = Ds + TM*ZZ*DP;          // [TM][128]  tanh(h@Wd1.T+bd1), idx = j*4+k
    float* d2s = d1s + TM*HH;            // [TM][128]
    float* bs  = d2s + TM*HH;            // [TM][128]

    const int tid  = threadIdx.x;
    const int warp = tid >> 5;
    const int lane = tid & 31;
    const int m0   = blockIdx.x * TM;

    // ---- load h tile: global coalesced read, padded-transpose store ----
    for (int idx = tid; idx < TM * HH; idx += NTHREADS) {
        int m = idx >> 7, hh = idx & 127;
        HsT[hh * 33 + m] = h[(size_t)(m0 + m) * HH + hh];
    }
    __syncthreads();

    // ---- small GEMMs: diag1, diag2, b  (lane = sample m, warp strides cols) ----
    for (int col = warp; col < 3 * HH; col += NWARPS) {
        int matid = col >> 7;       // 0:Wd1(tanh) 1:Wd2(tanh) 2:Wb
        int c = col & 127;
        const float* Wrow; float bias;
        if (matid == 0)      { Wrow = Wd1; bias = bd1[c]; }
        else if (matid == 1) { Wrow = Wd2; bias = bd2[c]; }
        else                 { Wrow = Wb;  bias = bb[c];  }
        const float4* w4 = (const float4*)(Wrow + (size_t)c * HH);
        float acc = bias;
        #pragma unroll 8
        for (int q = 0; q < 32; q++) {
            float4 w = w4[q];
            acc += HsT[(4*q+0)*33 + lane] * w.x
                 + HsT[(4*q+1)*33 + lane] * w.y
                 + HsT[(4*q+2)*33 + lane] * w.z
                 + HsT[(4*q+3)*33 + lane] * w.w;
        }
        if (matid < 2) acc = tanhf(acc);
        float* dst = (matid == 0) ? d1s : (matid == 1 ? d2s : bs);
        dst[lane * HH + c] = acc;
    }

    // ---- per-sample flow state in registers: warp owns samples warp*4+s ----
    float zreg[4], ldp[4];
    #pragma unroll
    for (int s = 0; s < 4; s++) {
        int m = warp * 4 + s;
        zreg[s] = z0[(size_t)(m0 + m) * ZZ + lane];
        ldp[s]  = 0.0f;
    }

    for (int k = 0; k < KK; k++) {
        __syncthreads();  // Ds free to overwrite; (k==0) small GEMMs done

        // ---- main GEMM: Ds[m][i*33+j] = h_m . Wd[(i*32+j)*4+k] + bd ----
        // each warp computes 8 consecutive columns for all 32 samples (lane = m)
        #pragma unroll 1
        for (int pass = 0; pass < 1024 / (NWARPS * 8); pass++) {
            int nbase = (pass * NWARPS + warp) * 8;
            float acc[8];
            const float4* w4[8];
            #pragma unroll
            for (int c = 0; c < 8; c++) {
                int row = (nbase + c) * KK + k;          // flat = i*128 + j*4 + k
                acc[c] = bd[row];
                w4[c]  = (const float4*)(Wd + (size_t)row * HH);
            }
            #pragma unroll 4
            for (int q = 0; q < 32; q++) {
                float h0 = HsT[(4*q+0)*33 + lane];
                float h1 = HsT[(4*q+1)*33 + lane];
                float h2 = HsT[(4*q+2)*33 + lane];
                float h3 = HsT[(4*q+3)*33 + lane];
                #pragma unroll
                for (int c = 0; c < 8; c++) {
                    float4 w = w4[c][q];                  // uniform across warp
                    acc[c] += h0*w.x + h1*w.y + h2*w.z + h3*w.w;
                }
            }
            int i = nbase >> 5, j0 = nbase & 31;          // 8 cols stay in one i row
            #pragma unroll
            for (int c = 0; c < 8; c++)
                Ds[lane * (ZZ*DP) + i * DP + j0 + c] = acc[c];
        }
        __syncthreads();

        // ---- flow step k ----
        const bool flip = (k & 1);
        #pragma unroll
        for (int s = 0; s < 4; s++) {
            int m = warp * 4 + s;
            const float* Dm = Ds + m * (ZZ*DP);
            // z_per[lane]
            float zp = flip ? __shfl_sync(0xffffffffu, zreg[s], 31 - lane) : zreg[s];
            // pre[j=lane] = b + z_per[j]*diag2[j] + sum_{i>j} z_per[i]*D[i][j]
            float pre = bs[m*HH + lane*KK + k] + zp * d2s[m*HH + lane*KK + k];
            #pragma unroll
            for (int i = 1; i < ZZ; i++) {
                float zpi = __shfl_sync(0xffffffffu, zp, i);
                if (i > lane) pre += zpi * Dm[i * DP + lane];
            }
            float t = tanhf(pre);
            // dz[i=lane] = t[i]*diag1[i] + sum_{j>i} t[j]*D[i][j]
            float d1  = d1s[m*HH + lane*KK + k];
            float d2v = d2s[m*HH + lane*KK + k];
            float dacc = t * d1;
            #pragma unroll
            for (int j = 1; j < ZZ; j++) {
                float tj = __shfl_sync(0xffffffffu, t, j);
                if (j > lane) dacc += tj * Dm[lane * DP + j];
            }
            float dz = flip ? __shfl_sync(0xffffffffu, dacc, 31 - lane) : dacc;
            zreg[s] += dz;
            // log-det contribution (index j = lane)
            float dj = fmaf(1.0f - t * t, d1 * d2v, 1.0f);
            ldp[s] += logf(fabsf(dj));
        }
    }

    // ---- outputs: z (B,32) then log_det (B,) ----
    #pragma unroll
    for (int s = 0; s < 4; s++) {
        int m = warp * 4 + s;
        out_z[(size_t)(m0 + m) * ZZ + lane] = zreg[s];
        float v = ldp[s];
        #pragma unroll
        for (int off = 16; off; off >>= 1)
            v += __shfl_down_sync(0xffffffffu, v, off);
        if (lane == 0) out_ld[m0 + m] = v;
    }
}

extern "C" void kernel_launch(void* const* d_in, const int* in_sizes, int n_in,
                              void* d_out, int out_size)
{
    const float* z0  = (const float*)d_in[0];
    const float* h   = (const float*)d_in[1];
    const float* Wd  = (const float*)d_in[2];
    const float* bd  = (const float*)d_in[3];
    const float* Wd1 = (const float*)d_in[4];
    const float* bd1 = (const float*)d_in[5];
    const float* Wd2 = (const float*)d_in[6];
    const float* bd2 = (const float*)d_in[7];
    const float* Wb  = (const float*)d_in[8];
    const float* bb  = (const float*)d_in[9];
    // d_in[10] = is_test (ignored; reference path with is_test=0)

    const int B = in_sizes[0] / ZZ;   // 32768
    float* out   = (float*)d_out;
    float* out_z = out;               // B*Z floats
    float* out_ld = out + (size_t)B * ZZ;

    cudaFuncSetAttribute(sylv_kernel,
                         cudaFuncAttributeMaxDynamicSharedMemorySize, SMEM_BYTES);

    sylv_kernel<<<B / TM, NTHREADS, SMEM_BYTES>>>(
        z0, h, Wd, bd, Wd1, bd1, Wd2, bd2, Wb, bb, out_z, out_ld);
}

// round 5
// speedup vs baseline: 6.3684x; 6.3678x over previous
#include <cuda_runtime.h>
#include <cuda_bf16.h>
#include <stdint.h>
#include <math.h>

// TriangularSylvesterNeRF  Z=32 K=4 H=128 B=32768
// mma.sync.m16n8k16 bf16 split-precision path (compute_103-safe, no tcgen05).

#define ZZ 32
#define KK 4
#define HH 128
#define TM 64
#define NTH 256
#define DPITCH 129

// ---- smem byte offsets ----
#define OFF_B    0              /* B frag hi, 32KB */
#define OFF_BLO  32768          /* B frag lo, 32KB */
#define OFF_D    65536          /* Ds   [64][129] f32 */
#define OFF_D1   98560          /* d1s  (tanh'd)      */
#define OFF_D2   131584         /* d2s  (tanh'd)      */
#define OFF_BSM  164608         /* bs   (biased)      */
#define OFF_BD   197632         /* bd reordered [4][8][128] f32 */
#define OFF_BDG  214016         /* diag biases [3][128] f32     */
#define OFF_Z    215552         /* zsm [64][33] f32             */
#define SMEM_TOTAL 224000

// ---- fragment-linear weight images ----
// entry uint2 = {b0, b1} for (kstep ks, global ntile nt, lane):
//   b0 = {W[n][16ks+2t], W[n][16ks+2t+1]}, b1 = {.. +8, +9}, n = nt*8 + (lane>>2)
__device__ uint2 g_WmHi[KK][8][128][32];
__device__ uint2 g_WmLo[KK][8][128][32];
__device__ uint2 g_WgHi[3][128][32];
__device__ uint2 g_WgLo[3][128][32];
__device__ float g_bdre[KK][8][128];
__device__ float g_bdiag[3][128];

__device__ __forceinline__ uint32_t pack2(float a, float b) {
    return (uint32_t)__bfloat16_as_ushort(__float2bfloat16(a)) |
           ((uint32_t)__bfloat16_as_ushort(__float2bfloat16(b)) << 16);
}
__device__ __forceinline__ float bres(float x) {
    return x - __bfloat162float(__float2bfloat16(x));
}

__global__ void prep_kernel(const float* __restrict__ Wd, const float* __restrict__ bd,
                            const float* __restrict__ Wd1, const float* __restrict__ bd1,
                            const float* __restrict__ Wd2, const float* __restrict__ bd2,
                            const float* __restrict__ Wb, const float* __restrict__ bb)
{
    int idx = blockIdx.x * blockDim.x + threadIdx.x;
    if (idx < 131072) {                      // main weights, frag entries
        int lane = idx & 31, slot = (idx >> 5) & 127, c = (idx >> 12) & 7, k = idx >> 15;
        int ks = slot >> 4, nt = slot & 15, g = lane >> 2, t = lane & 3;
        int n = nt * 8 + g, jj = n >> 5, i = n & 31, j = c * 4 + jj;
        const float* src = Wd + (size_t)((i * ZZ + j) * KK + k) * HH + ks * 16 + 2 * t;
        float f0 = src[0], f1 = src[1], f2 = src[8], f3 = src[9];
        g_WmHi[k][c][slot][lane] = make_uint2(pack2(f0, f1), pack2(f2, f3));
        g_WmLo[k][c][slot][lane] = make_uint2(pack2(bres(f0), bres(f1)),
                                              pack2(bres(f2), bres(f3)));
    } else if (idx < 131072 + 12288) {       // diag weights
        int r = idx - 131072;
        int lane = r & 31, slot = (r >> 5) & 127, m = r >> 12;
        int ks = slot >> 4, nt = slot & 15, g = lane >> 2, t = lane & 3;
        int n = nt * 8 + g, kq = n >> 5, j = n & 31;
        const float* W = (m == 0) ? Wd1 : (m == 1) ? Wd2 : Wb;
        const float* src = W + (size_t)(j * KK + kq) * HH + ks * 16 + 2 * t;
        float f0 = src[0], f1 = src[1], f2 = src[8], f3 = src[9];
        g_WgHi[m][slot][lane] = make_uint2(pack2(f0, f1), pack2(f2, f3));
        g_WgLo[m][slot][lane] = make_uint2(pack2(bres(f0), bres(f1)),
                                           pack2(bres(f2), bres(f3)));
    } else if (idx < 131072 + 12288 + 4096) {  // main biases
        int r = idx - 131072 - 12288;            // [k][c][n]
        int n = r & 127, c = (r >> 7) & 7, k = r >> 10;
        int jj = n >> 5, i = n & 31, j = c * 4 + jj;
        g_bdre[k][c][n] = bd[(i * ZZ + j) * KK + k];
    } else if (idx < 131072 + 12288 + 4096 + 384) {  // diag biases
        int r = idx - 147456;
        int n = r & 127, m = r >> 7;
        int kq = n >> 5, j = n & 31;
        const float* bv = (m == 0) ? bd1 : (m == 1) ? bd2 : bb;
        g_bdiag[m][n] = bv[j * KK + kq];
    }
}

__device__ __forceinline__ void mma_bf16(float c[4], const uint32_t a[4],
                                         uint32_t b0, uint32_t b1) {
    asm volatile(
        "mma.sync.aligned.m16n8k16.row.col.f32.bf16.bf16.f32 "
        "{%0,%1,%2,%3}, {%4,%5,%6,%7}, {%8,%9}, {%0,%1,%2,%3};"
        : "+f"(c[0]), "+f"(c[1]), "+f"(c[2]), "+f"(c[3])
        : "r"(a[0]), "r"(a[1]), "r"(a[2]), "r"(a[3]), "r"(b0), "r"(b1));
}

__global__ __launch_bounds__(NTH, 1)
void sylv_main(const float* __restrict__ z0, const float* __restrict__ h,
               float* __restrict__ out_z, float* __restrict__ out_ld)
{
    extern __shared__ char sm[];
    float* Ds  = (float*)(sm + OFF_D);
    float* d1s = (float*)(sm + OFF_D1);
    float* d2s = (float*)(sm + OFF_D2);
    float* bsm = (float*)(sm + OFF_BSM);
    float* bds = (float*)(sm + OFF_BD);
    float* bdg = (float*)(sm + OFF_BDG);
    float* zsm = (float*)(sm + OFF_Z);
    uint2* Bh  = (uint2*)(sm + OFF_B);
    uint2* Bl  = (uint2*)(sm + OFF_BLO);

    const int tid = threadIdx.x, w = tid >> 5, lane = tid & 31;
    const int g = lane >> 2, t = lane & 3;
    const int r0  = (w & 3) * 16;       // row base (samples)
    const int nt0 = (w >> 2) * 8;       // global ntile base
    const int cb  = nt0 * 8;            // col base
    const int m0  = blockIdx.x * TM;

    // ---- A fragments (persist all chunks): split bf16 hi/lo ----
    uint32_t aH[8][4], aL[8][4];
    {
        const float* hp = h + (size_t)m0 * HH;
        #pragma unroll
        for (int ks = 0; ks < 8; ks++) {
            int k0 = ks * 16 + 2 * t;
            const float* p0 = hp + (size_t)(r0 + g) * HH + k0;
            const float* p1 = hp + (size_t)(r0 + g + 8) * HH + k0;
            float2 x0 = *(const float2*)p0;
            float2 x1 = *(const float2*)p1;
            float2 x2 = *(const float2*)(p0 + 8);
            float2 x3 = *(const float2*)(p1 + 8);
            aH[ks][0] = pack2(x0.x, x0.y); aL[ks][0] = pack2(bres(x0.x), bres(x0.y));
            aH[ks][1] = pack2(x1.x, x1.y); aL[ks][1] = pack2(bres(x1.x), bres(x1.y));
            aH[ks][2] = pack2(x2.x, x2.y); aL[ks][2] = pack2(bres(x2.x), bres(x2.y));
            aH[ks][3] = pack2(x3.x, x3.y); aL[ks][3] = pack2(bres(x3.x), bres(x3.y));
        }
    }
    // ---- biases + z into smem ----
    for (int i2 = tid; i2 < 4096; i2 += NTH) bds[i2] = ((const float*)g_bdre)[i2];
    for (int i2 = tid; i2 < 384; i2 += NTH)  bdg[i2] = ((const float*)g_bdiag)[i2];
    if (tid < TM) {
        const float* zr = z0 + (size_t)(m0 + tid) * ZZ;
        #pragma unroll
        for (int i = 0; i < ZZ; i++) zsm[tid * 33 + i] = zr[i];
    }

    // ---- diag chunks: d1 (tanh), d2 (tanh), b ----
    for (int m = 0; m < 3; m++) {
        __syncthreads();
        {
            const uint4* sh = (const uint4*)&g_WgHi[m][0][0];
            const uint4* sl = (const uint4*)&g_WgLo[m][0][0];
            uint4* dh = (uint4*)(sm + OFF_B); uint4* dl = (uint4*)(sm + OFF_BLO);
            for (int i2 = tid; i2 < 2048; i2 += NTH) { dh[i2] = sh[i2]; dl[i2] = sl[i2]; }
        }
        __syncthreads();
        float acc[8][4];
        #pragma unroll
        for (int q = 0; q < 8; q++) acc[q][0] = acc[q][1] = acc[q][2] = acc[q][3] = 0.f;
        #pragma unroll
        for (int ks = 0; ks < 8; ks++) {
            #pragma unroll
            for (int ntl = 0; ntl < 8; ntl++) {
                int slot = ks * 16 + nt0 + ntl;
                uint2 bh = Bh[slot * 32 + lane];
                uint2 bl = Bl[slot * 32 + lane];
                mma_bf16(acc[ntl], aH[ks], bh.x, bh.y);
                mma_bf16(acc[ntl], aH[ks], bl.x, bl.y);
                mma_bf16(acc[ntl], aL[ks], bh.x, bh.y);
            }
        }
        float* dst = (m == 0) ? d1s : (m == 1) ? d2s : bsm;
        #pragma unroll
        for (int ntl = 0; ntl < 8; ntl++) {
            int n0 = cb + ntl * 8 + 2 * t;
            float b0v = bdg[m * 128 + n0], b1v = bdg[m * 128 + n0 + 1];
            float v0 = acc[ntl][0] + b0v, v1 = acc[ntl][1] + b1v;
            float v2 = acc[ntl][2] + b0v, v3 = acc[ntl][3] + b1v;
            if (m < 2) { v0 = tanhf(v0); v1 = tanhf(v1); v2 = tanhf(v2); v3 = tanhf(v3); }
            dst[(r0 + g) * DPITCH + n0]     = v0;
            dst[(r0 + g) * DPITCH + n0 + 1] = v1;
            dst[(r0 + g + 8) * DPITCH + n0]     = v2;
            dst[(r0 + g + 8) * DPITCH + n0 + 1] = v3;
        }
    }
    // ---- stage main chunk 0 ----
    __syncthreads();
    {
        const uint4* sh = (const uint4*)&g_WmHi[0][0][0][0];
        const uint4* sl = (const uint4*)&g_WmLo[0][0][0][0];
        uint4* dh = (uint4*)(sm + OFF_B); uint4* dl = (uint4*)(sm + OFF_BLO);
        for (int i2 = tid; i2 < 2048; i2 += NTH) { dh[i2] = sh[i2]; dl[i2] = sl[i2]; }
    }
    __syncthreads();

    float zp[32], dz[32], ld_acc = 0.f;

    for (int cc = 0; cc < 32; cc++) {
        const int k = cc >> 3, c = cc & 7;
        const int flip = k & 1;

        // ---- GEMM chunk (all warps) ----
        float acc[8][4];
        #pragma unroll
        for (int q = 0; q < 8; q++) acc[q][0] = acc[q][1] = acc[q][2] = acc[q][3] = 0.f;
        #pragma unroll
        for (int ks = 0; ks < 8; ks++) {
            #pragma unroll
            for (int ntl = 0; ntl < 8; ntl++) {
                int slot = ks * 16 + nt0 + ntl;
                uint2 bh = Bh[slot * 32 + lane];
                uint2 bl = Bl[slot * 32 + lane];
                mma_bf16(acc[ntl], aH[ks], bh.x, bh.y);
                mma_bf16(acc[ntl], aH[ks], bl.x, bl.y);
                mma_bf16(acc[ntl], aL[ks], bh.x, bh.y);
            }
        }
        // store D with bd bias folded
        const float* bcol = bds + (k * 8 + c) * 128;
        #pragma unroll
        for (int ntl = 0; ntl < 8; ntl++) {
            int n0 = cb + ntl * 8 + 2 * t;
            float b0v = bcol[n0], b1v = bcol[n0 + 1];
            Ds[(r0 + g) * DPITCH + n0]     = acc[ntl][0] + b0v;
            Ds[(r0 + g) * DPITCH + n0 + 1] = acc[ntl][1] + b1v;
            Ds[(r0 + g + 8) * DPITCH + n0]     = acc[ntl][2] + b0v;
            Ds[(r0 + g + 8) * DPITCH + n0 + 1] = acc[ntl][3] + b1v;
        }
        __syncthreads();

        if (tid >= TM) {
            // ---- stage next B while flow runs ----
            if (cc + 1 < 32) {
                int k2 = (cc + 1) >> 3, c2 = (cc + 1) & 7;
                const uint4* sh = (const uint4*)&g_WmHi[k2][c2][0][0];
                const uint4* sl = (const uint4*)&g_WmLo[k2][c2][0][0];
                uint4* dh = (uint4*)(sm + OFF_B); uint4* dl = (uint4*)(sm + OFF_BLO);
                for (int i2 = tid - TM; i2 < 2048; i2 += (NTH - TM)) {
                    dh[i2] = sh[i2]; dl[i2] = sl[i2];
                }
            }
        } else {
            // ---- flow (thread == sample) ----
            const int m = tid;
            if (c == 0) {
                #pragma unroll
                for (int i = 0; i < 32; i++) {
                    zp[i] = zsm[m * 33 + (flip ? 31 - i : i)];
                    dz[i] = 0.f;
                }
            }
            #pragma unroll
            for (int jj = 0; jj < 4; jj++) {
                int j = c * 4 + jj, kj = k * 32 + j;
                float d1v = d1s[m * DPITCH + kj];
                float d2v = d2s[m * DPITCH + kj];
                float pre = bsm[m * DPITCH + kj];
                const float* drow = Ds + m * DPITCH + jj * 32;
                #pragma unroll
                for (int i = 0; i < 32; i++) {
                    float Dv = drow[i];
                    float coef = (i > j) ? Dv : ((i == j) ? d2v : 0.f);
                    pre = fmaf(zp[i], coef, pre);
                }
                float tt = tanhf(pre);
                ld_acc += logf(fabsf(fmaf(1.f - tt * tt, d1v * d2v, 1.f)));
                #pragma unroll
                for (int i = 0; i < 32; i++) {
                    float Dv = drow[i];
                    float coef = (i < j) ? Dv : ((i == j) ? d1v : 0.f);
                    dz[i] = fmaf(tt, coef, dz[i]);
                }
            }
            if (c == 7) {
                #pragma unroll
                for (int i = 0; i < 32; i++)
                    zsm[m * 33 + (flip ? 31 - i : i)] += dz[i];
            }
        }
        __syncthreads();
    }

    if (tid < TM) {
        float* oz = out_z + (size_t)(m0 + tid) * ZZ;
        #pragma unroll
        for (int i = 0; i < ZZ; i++) oz[i] = zsm[tid * 33 + i];
        out_ld[m0 + tid] = ld_acc;
    }
}

extern "C" void kernel_launch(void* const* d_in, const int* in_sizes, int n_in,
                              void* d_out, int out_size)
{
    const float* z0  = (const float*)d_in[0];
    const float* h   = (const float*)d_in[1];
    const float* Wd  = (const float*)d_in[2];
    const float* bd  = (const float*)d_in[3];
    const float* Wd1 = (const float*)d_in[4];
    const float* bd1 = (const float*)d_in[5];
    const float* Wd2 = (const float*)d_in[6];
    const float* bd2 = (const float*)d_in[7];
    const float* Wb  = (const float*)d_in[8];
    const float* bb  = (const float*)d_in[9];

    const int B = in_sizes[0] / ZZ;          // 32768
    float* out_z  = (float*)d_out;
    float* out_ld = (float*)d_out + (size_t)B * ZZ;

    int prep_elems = 131072 + 12288 + 4096 + 384;
    prep_kernel<<<(prep_elems + 255) / 256, 256>>>(Wd, bd, Wd1, bd1, Wd2, bd2, Wb, bb);

    cudaFuncSetAttribute(sylv_main, cudaFuncAttributeMaxDynamicSharedMemorySize, SMEM_TOTAL);
    sylv_main<<<B / TM, NTH, SMEM_TOTAL>>>(z0, h, out_z, out_ld);
}

// round 6
// speedup vs baseline: 6.5148x; 1.0230x over previous
#include <cuda_runtime.h>
#include <cuda_bf16.h>
#include <stdint.h>
#include <math.h>

// TriangularSylvesterNeRF  Z=32 K=4 H=128 B=32768
// mma.sync bf16 split-precision, fully pipelined (tensor/fma overlap).

#define ZZ 32
#define KK 4
#define HH 128
#define TM 64
#define NTH 256
#define NCTA 512
#define DP 132          /* D row pitch (floats) */

// ---- smem byte offsets ----
#define OFF_B0 0        /* hi 32K + lo 32K */
#define OFF_B1 65536
#define OFF_D0 131072   /* [64][132] f32 = 33792 */
#define OFF_D1 164864
#define OFF_Z  198656   /* [64][33] f32 = 8448 */
#define OFF_BB 207104   /* bias slots [2][128] f32 */
#define SMEM_TOTAL 208128

// ---- fragment-linear weight images (layout identical to round-5) ----
__device__ uint2 g_WmHi[KK][8][128][32];
__device__ uint2 g_WmLo[KK][8][128][32];
__device__ uint2 g_WgHi[3][128][32];
__device__ uint2 g_WgLo[3][128][32];
__device__ float g_bdre[KK][8][128];
__device__ float g_bdiag[3][128];
// per-CTA diag scratch: [blk][{d1,d2,b}][kj 0..127][sample 0..63]
__device__ float g_dg[NCTA][3][128][64];

__device__ __forceinline__ uint32_t pack2(float a, float b) {
    return (uint32_t)__bfloat16_as_ushort(__float2bfloat16(a)) |
           ((uint32_t)__bfloat16_as_ushort(__float2bfloat16(b)) << 16);
}
__device__ __forceinline__ float bres(float x) {
    return x - __bfloat162float(__float2bfloat16(x));
}

__global__ void prep_kernel(const float* __restrict__ Wd, const float* __restrict__ bd,
                            const float* __restrict__ Wd1, const float* __restrict__ bd1,
                            const float* __restrict__ Wd2, const float* __restrict__ bd2,
                            const float* __restrict__ Wb, const float* __restrict__ bb)
{
    int idx = blockIdx.x * blockDim.x + threadIdx.x;
    if (idx < 131072) {                      // main weights, frag entries
        int lane = idx & 31, slot = (idx >> 5) & 127, c = (idx >> 12) & 7, k = idx >> 15;
        int ks = slot >> 4, nt = slot & 15, g = lane >> 2, t = lane & 3;
        int n = nt * 8 + g, jj = n >> 5, i = n & 31, j = c * 4 + jj;
        const float* src = Wd + (size_t)((i * ZZ + j) * KK + k) * HH + ks * 16 + 2 * t;
        float f0 = src[0], f1 = src[1], f2 = src[8], f3 = src[9];
        g_WmHi[k][c][slot][lane] = make_uint2(pack2(f0, f1), pack2(f2, f3));
        g_WmLo[k][c][slot][lane] = make_uint2(pack2(bres(f0), bres(f1)),
                                              pack2(bres(f2), bres(f3)));
    } else if (idx < 131072 + 12288) {       // diag weights
        int r = idx - 131072;
        int lane = r & 31, slot = (r >> 5) & 127, m = r >> 12;
        int ks = slot >> 4, nt = slot & 15, g = lane >> 2, t = lane & 3;
        int n = nt * 8 + g, kq = n >> 5, j = n & 31;
        const float* W = (m == 0) ? Wd1 : (m == 1) ? Wd2 : Wb;
        const float* src = W + (size_t)(j * KK + kq) * HH + ks * 16 + 2 * t;
        float f0 = src[0], f1 = src[1], f2 = src[8], f3 = src[9];
        g_WgHi[m][slot][lane] = make_uint2(pack2(f0, f1), pack2(f2, f3));
        g_WgLo[m][slot][lane] = make_uint2(pack2(bres(f0), bres(f1)),
                                           pack2(bres(f2), bres(f3)));
    } else if (idx < 131072 + 12288 + 4096) {  // main biases [k][c][n]
        int r = idx - 131072 - 12288;
        int n = r & 127, c = (r >> 7) & 7, k = r >> 10;
        int jj = n >> 5, i = n & 31, j = c * 4 + jj;
        g_bdre[k][c][n] = bd[(i * ZZ + j) * KK + k];
    } else if (idx < 131072 + 12288 + 4096 + 384) {  // diag biases [m][kj]
        int r = idx - 147456;
        int n = r & 127, m = r >> 7;
        int kq = n >> 5, j = n & 31;
        const float* bv = (m == 0) ? bd1 : (m == 1) ? bd2 : bb;
        g_bdiag[m][n] = bv[j * KK + kq];
    }
}

__device__ __forceinline__ void mma_bf16(float c[4], const uint32_t a[4],
                                         uint32_t b0, uint32_t b1) {
    asm volatile(
        "mma.sync.aligned.m16n8k16.row.col.f32.bf16.bf16.f32 "
        "{%0,%1,%2,%3}, {%4,%5,%6,%7}, {%8,%9}, {%0,%1,%2,%3};"
        : "+f"(c[0]), "+f"(c[1]), "+f"(c[2]), "+f"(c[3])
        : "r"(a[0]), "r"(a[1]), "r"(a[2]), "r"(a[3]), "r"(b0), "r"(b1));
}

__device__ __forceinline__ void cp16(uint32_t dst, const void* src) {
    asm volatile("cp.async.cg.shared.global [%0], [%1], 16;" :: "r"(dst), "l"(src));
}
#define CP_COMMIT() asm volatile("cp.async.commit_group;" ::: "memory")
#define CP_WAIT0()  asm volatile("cp.async.wait_group 0;" ::: "memory")

__device__ __forceinline__ uint32_t smem_u32(const void* p) {
    uint32_t a;
    asm("{ .reg .u64 t; cvta.to.shared.u64 t, %1; cvt.u32.u64 %0, t; }" : "=r"(a) : "l"(p));
    return a;
}

__device__ __forceinline__ void gemm_chunk(const uint2* __restrict__ Bh,
                                           const uint2* __restrict__ Bl,
                                           int lane, int nt0,
                                           const uint32_t aH[8][4],
                                           const uint32_t aL[8][4],
                                           float acc[8][4])
{
    #pragma unroll
    for (int q = 0; q < 8; q++)
        acc[q][0] = acc[q][1] = acc[q][2] = acc[q][3] = 0.f;
    #pragma unroll
    for (int ks = 0; ks < 8; ks++) {
        #pragma unroll
        for (int ntl = 0; ntl < 8; ntl++) {
            int slot = ks * 16 + nt0 + ntl;
            uint2 bh = Bh[slot * 32 + lane];
            uint2 bl = Bl[slot * 32 + lane];
            mma_bf16(acc[ntl], aH[ks], bh.x, bh.y);
            mma_bf16(acc[ntl], aH[ks], bl.x, bl.y);
            mma_bf16(acc[ntl], aL[ks], bh.x, bh.y);
        }
    }
}

// stage main chunk (k2,c2) + its bias into buffer `buf` (async)
__device__ __forceinline__ void stage_async(uint32_t sb, int buf, int k2, int c2, int tid) {
    const char* sh = (const char*)&g_WmHi[k2][c2][0][0];
    const char* sl = (const char*)&g_WmLo[k2][c2][0][0];
    uint32_t dh = sb + (buf ? OFF_B1 : OFF_B0);
    uint32_t dl = dh + 32768;
    #pragma unroll
    for (int r = 0; r < 8; r++) {
        int i = r * NTH + tid;
        cp16(dh + i * 16, sh + i * 16);
        cp16(dl + i * 16, sl + i * 16);
    }
    if (tid < 32)
        cp16(sb + OFF_BB + buf * 512 + tid * 16,
             (const char*)&g_bdre[k2][c2][0] + tid * 16);
}

__global__ __launch_bounds__(NTH, 1)
void sylv_main(const float* __restrict__ z0, const float* __restrict__ h,
               float* __restrict__ out_z, float* __restrict__ out_ld)
{
    extern __shared__ char sm[];
    const uint32_t sb = smem_u32(sm);
    float* zsm = (float*)(sm + OFF_Z);

    const int tid = threadIdx.x, w = tid >> 5, lane = tid & 31;
    const int g = lane >> 2, t = lane & 3;
    const int r0  = (w & 3) * 16;          // GEMM row base
    const int nt0 = (w >> 2) * 8;          // GEMM ntile base
    const int cb  = nt0 * 8;               // GEMM col base
    const int blk = blockIdx.x;
    const int m0  = blk * TM;
    const int msamp = tid >> 2, q = tid & 3;   // flow: sample / quarter

    // ---- A fragments (persist): split bf16 hi/lo ----
    uint32_t aH[8][4], aL[8][4];
    {
        const float* hp = h + (size_t)m0 * HH;
        #pragma unroll
        for (int ks = 0; ks < 8; ks++) {
            int k0 = ks * 16 + 2 * t;
            const float* p0 = hp + (size_t)(r0 + g) * HH + k0;
            const float* p1 = hp + (size_t)(r0 + g + 8) * HH + k0;
            float2 x0 = *(const float2*)p0;
            float2 x1 = *(const float2*)p1;
            float2 x2 = *(const float2*)(p0 + 8);
            float2 x3 = *(const float2*)(p1 + 8);
            aH[ks][0] = pack2(x0.x, x0.y); aL[ks][0] = pack2(bres(x0.x), bres(x0.y));
            aH[ks][1] = pack2(x1.x, x1.y); aL[ks][1] = pack2(bres(x1.x), bres(x1.y));
            aH[ks][2] = pack2(x2.x, x2.y); aL[ks][2] = pack2(bres(x2.x), bres(x2.y));
            aH[ks][3] = pack2(x3.x, x3.y); aL[ks][3] = pack2(bres(x3.x), bres(x3.y));
        }
    }
    // ---- z into smem ----
    for (int idx = tid; idx < TM * ZZ; idx += NTH)
        zsm[(idx >> 5) * 33 + (idx & 31)] = z0[(size_t)(m0 + (idx >> 5)) * ZZ + (idx & 31)];

    const uint2* Bh0 = (const uint2*)(sm + OFF_B0);
    const uint2* Bl0 = (const uint2*)(sm + OFF_B0 + 32768);
    const uint2* Bh1 = (const uint2*)(sm + OFF_B1);
    const uint2* Bl1 = (const uint2*)(sm + OFF_B1 + 32768);

    // ---- diag GEMMs -> global scratch ----
    for (int mm = 0; mm < 3; mm++) {
        {
            const char* sh = (const char*)&g_WgHi[mm][0][0];
            const char* sl = (const char*)&g_WgLo[mm][0][0];
            #pragma unroll
            for (int r = 0; r < 8; r++) {
                int i = r * NTH + tid;
                cp16(sb + OFF_B0 + i * 16, sh + i * 16);
                cp16(sb + OFF_B0 + 32768 + i * 16, sl + i * 16);
            }
        }
        CP_COMMIT(); CP_WAIT0();
        __syncthreads();
        float acc[8][4];
        gemm_chunk(Bh0, Bl0, lane, nt0, aH, aL, acc);
        #pragma unroll
        for (int ntl = 0; ntl < 8; ntl++) {
            int n0 = cb + ntl * 8 + 2 * t;
            float b0v = g_bdiag[mm][n0], b1v = g_bdiag[mm][n0 + 1];
            float v0 = acc[ntl][0] + b0v, v1 = acc[ntl][1] + b1v;
            float v2 = acc[ntl][2] + b0v, v3 = acc[ntl][3] + b1v;
            if (mm < 2) { v0 = tanhf(v0); v1 = tanhf(v1); v2 = tanhf(v2); v3 = tanhf(v3); }
            g_dg[blk][mm][n0][r0 + g]         = v0;
            g_dg[blk][mm][n0 + 1][r0 + g]     = v1;
            g_dg[blk][mm][n0][r0 + g + 8]     = v2;
            g_dg[blk][mm][n0 + 1][r0 + g + 8] = v3;
        }
        __syncthreads();
    }

    // ---- stage B0,B1; GEMM chunk 0 -> D0 ----
    stage_async(sb, 0, 0, 0, tid);
    stage_async(sb, 1, 0, 1, tid);
    CP_COMMIT(); CP_WAIT0();
    __syncthreads();
    {
        float acc[8][4];
        gemm_chunk(Bh0, Bl0, lane, nt0, aH, aL, acc);
        float* Dd = (float*)(sm + OFF_D0);
        const float* bbp = (const float*)(sm + OFF_BB);
        #pragma unroll
        for (int ntl = 0; ntl < 8; ntl++) {
            int n0 = cb + ntl * 8 + 2 * t;
            float b0v = bbp[n0], b1v = bbp[n0 + 1];
            *(float2*)&Dd[(r0 + g) * DP + n0]     = make_float2(acc[ntl][0] + b0v, acc[ntl][1] + b1v);
            *(float2*)&Dd[(r0 + g + 8) * DP + n0] = make_float2(acc[ntl][2] + b0v, acc[ntl][3] + b1v);
        }
    }
    __syncthreads();

    // ---- main pipelined loop ----
    float zp[8], dz[8], ld_acc = 0.f;

    #pragma unroll 1
    for (int cc = 0; cc < 32; cc++) {
        const int k = cc >> 3, c = cc & 7, flip = k & 1;
        const int nx = cc + 1;
        const int jbase = c * 4;

        // diag prefetch for flow chunk cc (long-latency LDG issued early)
        const int kjq = k * 32 + jbase + q;
        float d2m = g_dg[blk][1][kjq][msamp];
        float bm  = g_dg[blk][2][kjq][msamp];
        float d1a[4];
        #pragma unroll
        for (int jj = 0; jj < 4; jj++)
            d1a[jj] = g_dg[blk][0][k * 32 + jbase + jj][msamp];

        // stage chunk cc+2 under the MMAs
        if (cc <= 29) stage_async(sb, cc & 1, (cc + 2) >> 3, (cc + 2) & 7, tid);

        // GEMM chunk nx (tensor pipe)
        float acc[8][4];
        if (nx < 32)
            gemm_chunk((nx & 1) ? Bh1 : Bh0, (nx & 1) ? Bl1 : Bl0,
                       lane, nt0, aH, aL, acc);

        // ---- flow chunk cc (fma pipe, overlaps MMA drain) ----
        {
            const float* Dc = (const float*)(sm + ((cc & 1) ? OFF_D1 : OFF_D0));
            if (c == 0) {
                #pragma unroll
                for (int il = 0; il < 8; il++) {
                    int gi = q * 8 + il;
                    zp[il] = zsm[msamp * 33 + (flip ? 31 - gi : gi)];
                    dz[il] = 0.f;
                }
            }
            float zpj = zsm[msamp * 33 + (flip ? 31 - (jbase + q) : (jbase + q))];

            float Dv[4][8];
            #pragma unroll
            for (int jj = 0; jj < 4; jj++) {
                const float4* p = (const float4*)&Dc[msamp * DP + jj * 32 + q * 8];
                float4 x = p[0], y = p[1];
                Dv[jj][0] = x.x; Dv[jj][1] = x.y; Dv[jj][2] = x.z; Dv[jj][3] = x.w;
                Dv[jj][4] = y.x; Dv[jj][5] = y.y; Dv[jj][6] = y.z; Dv[jj][7] = y.w;
            }
            float part[4];
            #pragma unroll
            for (int jj = 0; jj < 4; jj++) {
                int j = jbase + jj;
                float s = 0.f;
                #pragma unroll
                for (int il = 0; il < 8; il++) {
                    int gi = q * 8 + il;
                    s = fmaf(zp[il], (gi > j) ? Dv[jj][il] : 0.f, s);
                }
                part[jj] = s;
            }
            #pragma unroll
            for (int jj = 0; jj < 4; jj++) {
                part[jj] += __shfl_xor_sync(0xffffffffu, part[jj], 1);
                part[jj] += __shfl_xor_sync(0xffffffffu, part[jj], 2);
            }
            float prem = (q == 0) ? part[0] : (q == 1) ? part[1]
                       : (q == 2) ? part[2] : part[3];
            float d1m  = (q == 0) ? d1a[0] : (q == 1) ? d1a[1]
                       : (q == 2) ? d1a[2] : d1a[3];
            prem += bm + zpj * d2m;
            float tm = tanhf(prem);
            ld_acc += logf(fabsf(fmaf(1.f - tm * tm, d1m * d2m, 1.f)));
            float ta = __shfl_xor_sync(0xffffffffu, tm, 1);
            float tb = __shfl_xor_sync(0xffffffffu, tm, 2);
            float tc = __shfl_xor_sync(0xffffffffu, ta, 2);
            #pragma unroll
            for (int jj = 0; jj < 4; jj++) {
                int j = jbase + jj, sel = jj ^ q;
                float tj = (sel == 0) ? tm : (sel == 1) ? ta : (sel == 2) ? tb : tc;
                #pragma unroll
                for (int il = 0; il < 8; il++) {
                    int gi = q * 8 + il;
                    float coef = (gi < j) ? Dv[jj][il] : ((gi == j) ? d1a[jj] : 0.f);
                    dz[il] = fmaf(tj, coef, dz[il]);
                }
            }
            if (c == 7) {
                #pragma unroll
                for (int il = 0; il < 8; il++) {
                    int gi = q * 8 + il;
                    zsm[msamp * 33 + (flip ? 31 - gi : gi)] += dz[il];
                }
            }
        }

        // store GEMM result for chunk nx
        if (nx < 32) {
            float* Dd = (float*)(sm + ((nx & 1) ? OFF_D1 : OFF_D0));
            const float* bbp = (const float*)(sm + OFF_BB + (nx & 1) * 512);
            #pragma unroll
            for (int ntl = 0; ntl < 8; ntl++) {
                int n0 = cb + ntl * 8 + 2 * t;
                float b0v = bbp[n0], b1v = bbp[n0 + 1];
                *(float2*)&Dd[(r0 + g) * DP + n0]     = make_float2(acc[ntl][0] + b0v, acc[ntl][1] + b1v);
                *(float2*)&Dd[(r0 + g + 8) * DP + n0] = make_float2(acc[ntl][2] + b0v, acc[ntl][3] + b1v);
            }
        }
        CP_COMMIT(); CP_WAIT0();
        __syncthreads();
    }

    // ---- outputs ----
    float v = ld_acc;
    v += __shfl_xor_sync(0xffffffffu, v, 1);
    v += __shfl_xor_sync(0xffffffffu, v, 2);
    if (q == 0) out_ld[m0 + msamp] = v;
    for (int idx = tid; idx < TM * ZZ; idx += NTH)
        out_z[(size_t)(m0 + (idx >> 5)) * ZZ + (idx & 31)] = zsm[(idx >> 5) * 33 + (idx & 31)];
}

extern "C" void kernel_launch(void* const* d_in, const int* in_sizes, int n_in,
                              void* d_out, int out_size)
{
    const float* z0  = (const float*)d_in[0];
    const float* h   = (const float*)d_in[1];
    const float* Wd  = (const float*)d_in[2];
    const float* bd  = (const float*)d_in[3];
    const float* Wd1 = (const float*)d_in[4];
    const float* bd1 = (const float*)d_in[5];
    const float* Wd2 = (const float*)d_in[6];
    const float* bd2 = (const float*)d_in[7];
    const float* Wb  = (const float*)d_in[8];
    const float* bb  = (const float*)d_in[9];

    const int B = in_sizes[0] / ZZ;          // 32768
    float* out_z  = (float*)d_out;
    float* out_ld = (float*)d_out + (size_t)B * ZZ;

    int prep_elems = 131072 + 12288 + 4096 + 384;
    prep_kernel<<<(prep_elems + 255) / 256, 256>>>(Wd, bd, Wd1, bd1, Wd2, bd2, Wb, bb);

    cudaFuncSetAttribute(sylv_main, cudaFuncAttributeMaxDynamicSharedMemorySize, SMEM_TOTAL);
    sylv_main<<<B / TM, NTH, SMEM_TOTAL>>>(z0, h, out_z, out_ld);
}